// round 2
// baseline (speedup 1.0000x reference)
#include <cuda_runtime.h>

// Problem constants (this instance): N=1e6 atoms, D=128, H=64, E=4, M=20000.
#define D_DIM 128
#define H_DIM 64
#define BM 128          // atoms per tile
#define BN 64           // hidden units per tile (== H)
#define BK 16           // k-slice
#define NTHREADS 256
#define E_MAX 8
#define PERM_CAP 1250000

// Scratch (static device globals — no allocation in kernel_launch)
__device__ int g_count[E_MAX];
__device__ int g_cursor[E_MAX];
__device__ int g_perm[PERM_CAP];

// packed fp32x2 FMA (Blackwell FFMA2 — only reachable via PTX)
#define FMA_F32X2(d, a, b, c) \
    asm("fma.rn.f32x2 %0, %1, %2, %3;" : "=l"(d) : "l"(a), "l"(b), "l"(c))

__device__ __forceinline__ float2 unpack_f32x2(unsigned long long u) {
    float2 f;
    asm("mov.b64 {%0, %1}, %2;" : "=f"(f.x), "=f"(f.y) : "l"(u));
    return f;
}

// ---------------------------------------------------------------------------
// init: zero output, zero histogram, fill perm slots with -1 sentinel
// ---------------------------------------------------------------------------
__global__ void k_init(float* __restrict__ out, int M, int total_slots) {
    int i = blockIdx.x * blockDim.x + threadIdx.x;
    int stride = gridDim.x * blockDim.x;
    for (int j = i; j < M; j += stride) out[j] = 0.0f;
    for (int j = i; j < total_slots; j += stride) g_perm[j] = -1;
    if (i < E_MAX) g_count[i] = 0;
}

// ---------------------------------------------------------------------------
// histogram of zidx (E bins)
// ---------------------------------------------------------------------------
__global__ void k_hist(const int* __restrict__ zidx, int n, int E) {
    __shared__ int sh[E_MAX];
    if (threadIdx.x < E_MAX) sh[threadIdx.x] = 0;
    __syncthreads();
    int i = blockIdx.x * blockDim.x + threadIdx.x;
    int stride = gridDim.x * blockDim.x;
    for (int j = i; j < n; j += stride) atomicAdd(&sh[zidx[j]], 1);
    __syncthreads();
    if (threadIdx.x < E) atomicAdd(&g_count[threadIdx.x], sh[threadIdx.x]);
}

// ---------------------------------------------------------------------------
// tiny exclusive scan with tile-padding of each element segment
// ---------------------------------------------------------------------------
__global__ void k_scan(int E) {
    if (blockIdx.x == 0 && threadIdx.x == 0) {
        int off = 0;
        for (int e = 0; e < E; e++) {
            g_cursor[e] = off;
            off += ((g_count[e] + BM - 1) / BM) * BM;
        }
    }
}

// ---------------------------------------------------------------------------
// scatter: block-aggregated counting-sort scatter of atom indices
// ---------------------------------------------------------------------------
__global__ void k_scatter(const int* __restrict__ zidx, int n) {
    __shared__ int s_cnt[E_MAX];
    __shared__ int s_off[E_MAX];
    if (threadIdx.x < E_MAX) s_cnt[threadIdx.x] = 0;
    __syncthreads();
    int i = blockIdx.x * blockDim.x + threadIdx.x;
    int e = -1;
    if (i < n) { e = zidx[i]; atomicAdd(&s_cnt[e], 1); }
    __syncthreads();
    if (threadIdx.x < E_MAX && s_cnt[threadIdx.x] > 0)
        s_off[threadIdx.x] = atomicAdd(&g_cursor[threadIdx.x], s_cnt[threadIdx.x]);
    __syncthreads();
    if (threadIdx.x < E_MAX) s_cnt[threadIdx.x] = 0;
    __syncthreads();
    if (i < n) {
        int pos = s_off[e] + atomicAdd(&s_cnt[e], 1);
        g_perm[pos] = i;
    }
}

// shifted softplus: softplus(x) - log(2), numerically stable
__device__ __forceinline__ float sspf(float v) {
    return fmaxf(v, 0.0f) + log1pf(__expf(-fabsf(v))) - 0.69314718055994530942f;
}

// ---------------------------------------------------------------------------
// main fused kernel: gathered SGEMM tile (128x64x128) with packed f32x2 FMAs
// + ssp + W2 dot + atomic segment add. Tiles are single-element by sort.
// ---------------------------------------------------------------------------
__global__ __launch_bounds__(NTHREADS)
void k_main(const float* __restrict__ x, const int* __restrict__ zidx,
            const int* __restrict__ idx_m,
            const float* __restrict__ W1, const float* __restrict__ b1,
            const float* __restrict__ W2, const float* __restrict__ b2,
            float* __restrict__ out) {
    __shared__ float Xs[BK][BM + 4];    // x-tile transposed: Xs[k][m]
    __shared__ float Wd[BK][2 * BN];    // W1 slice, each value DUPLICATED
    __shared__ int   s_orig[BM];
    __shared__ int   s_e;

    int tid = threadIdx.x;
    int base_slot = blockIdx.x * BM;

    if (tid < BM) s_orig[tid] = g_perm[base_slot + tid];
    if (tid == 0) {
        int e = -1;
        for (int r = 0; r < BM; r++) {
            int o = g_perm[base_slot + r];
            if (o >= 0) { e = zidx[o]; break; }
        }
        s_e = e;
    }
    __syncthreads();
    int e = s_e;
    if (e < 0) return;  // padding-only tile (uniform exit)

    const float* W1e = W1 + (size_t)e * D_DIM * H_DIM;
    const float* b1e = b1 + e * H_DIM;
    const float* W2e = W2 + e * H_DIM;
    float b2e = b2[e];

    int tx = tid & 15;   // column group: cols tx*4 .. tx*4+3
    int ty = tid >> 4;   // row group:    rows ty*8 .. ty*8+7

    // acc2[m2][n]: f32x2 over the m (row) dimension, rows (2*m2, 2*m2+1)
    unsigned long long acc2[4][4];
#pragma unroll
    for (int m2 = 0; m2 < 4; m2++)
#pragma unroll
        for (int n = 0; n < 4; n++) acc2[m2][n] = 0ull;

    for (int k0 = 0; k0 < D_DIM; k0 += BK) {
        // --- gather x tile (512 float4, 2 per thread), store transposed ---
#pragma unroll
        for (int t = 0; t < 2; t++) {
            int idx = tid * 2 + t;
            int row = idx >> 2;       // 0..127
            int kv  = idx & 3;        // which float4 within the BK slice
            int o = s_orig[row];
            float4 v = make_float4(0.f, 0.f, 0.f, 0.f);
            if (o >= 0)
                v = *reinterpret_cast<const float4*>(x + (size_t)o * D_DIM + k0 + kv * 4);
            int kk = kv * 4;
            Xs[kk + 0][row] = v.x;
            Xs[kk + 1][row] = v.y;
            Xs[kk + 2][row] = v.z;
            Xs[kk + 3][row] = v.w;
        }
        // --- load W1 slice (coalesced float4), store DUPLICATED ---
        {
            int kk = tid >> 4;    // 0..15
            int jv = tid & 15;    // 0..15 -> cols jv*4..jv*4+3
            float4 w = *reinterpret_cast<const float4*>(
                W1e + (size_t)(k0 + kk) * H_DIM + jv * 4);
            *reinterpret_cast<float4*>(&Wd[kk][jv * 8]) =
                make_float4(w.x, w.x, w.y, w.y);
            *reinterpret_cast<float4*>(&Wd[kk][jv * 8 + 4]) =
                make_float4(w.z, w.z, w.w, w.w);
        }
        __syncthreads();

#pragma unroll
        for (int kk = 0; kk < BK; kk++) {
            // a: 8 consecutive rows -> 4 f32x2, loaded pre-packed
            ulonglong2 a01 = *reinterpret_cast<const ulonglong2*>(&Xs[kk][ty * 8]);
            ulonglong2 a23 = *reinterpret_cast<const ulonglong2*>(&Xs[kk][ty * 8 + 4]);
            // b: 4 duplicated weights -> 4 f32x2, loaded pre-packed
            ulonglong2 b01 = *reinterpret_cast<const ulonglong2*>(&Wd[kk][tx * 8]);
            ulonglong2 b23 = *reinterpret_cast<const ulonglong2*>(&Wd[kk][tx * 8 + 4]);
            unsigned long long ap[4] = {a01.x, a01.y, a23.x, a23.y};
            unsigned long long bp[4] = {b01.x, b01.y, b23.x, b23.y};
#pragma unroll
            for (int m2 = 0; m2 < 4; m2++)
#pragma unroll
                for (int n = 0; n < 4; n++)
                    FMA_F32X2(acc2[m2][n], ap[m2], bp[n], acc2[m2][n]);
        }
        __syncthreads();
    }

    // --- epilogue: bias, ssp, dot with W2, reduce across tx, atomic add ---
    float4 b1v = *reinterpret_cast<const float4*>(b1e + tx * 4);
    float4 w2v = *reinterpret_cast<const float4*>(W2e + tx * 4);
    float bb[4] = {b1v.x, b1v.y, b1v.z, b1v.w};
    float ww[4] = {w2v.x, w2v.y, w2v.z, w2v.w};

    float part[8];
#pragma unroll
    for (int m2 = 0; m2 < 4; m2++) {
        float p0 = 0.0f, p1 = 0.0f;
#pragma unroll
        for (int n = 0; n < 4; n++) {
            float2 f = unpack_f32x2(acc2[m2][n]);
            p0 = fmaf(sspf(f.x + bb[n]), ww[n], p0);
            p1 = fmaf(sspf(f.y + bb[n]), ww[n], p1);
        }
        part[2 * m2]     = p0;
        part[2 * m2 + 1] = p1;
    }
    // reduce over the 16 tx-lanes (stays within each half-warp / same ty)
#pragma unroll
    for (int s = 8; s > 0; s >>= 1)
#pragma unroll
        for (int m = 0; m < 8; m++)
            part[m] += __shfl_xor_sync(0xffffffffu, part[m], s);

    if (tx == 0) {
#pragma unroll
        for (int m = 0; m < 8; m++) {
            int row = ty * 8 + m;
            int o = s_orig[row];
            if (o >= 0) atomicAdd(&out[idx_m[o]], part[m] + b2e);
        }
    }
}

// ---------------------------------------------------------------------------
extern "C" void kernel_launch(void* const* d_in, const int* in_sizes, int n_in,
                              void* d_out, int out_size) {
    const float* x    = (const float*)d_in[0];
    const int*   zidx = (const int*)d_in[1];
    const int*   idxm = (const int*)d_in[2];
    const float* W1   = (const float*)d_in[3];
    const float* b1   = (const float*)d_in[4];
    const float* W2   = (const float*)d_in[5];
    const float* b2   = (const float*)d_in[6];
    float* out = (float*)d_out;

    int N = in_sizes[1];        // number of atoms
    int E = in_sizes[6];        // number of elements (b2 has E entries)
    int M = out_size;           // number of molecules

    int ntiles = (N + BM - 1) / BM + E;    // worst case: each segment pads one tile
    int total_slots = ntiles * BM;
    if (total_slots > PERM_CAP) total_slots = PERM_CAP;  // defensive

    k_init<<<256, 256>>>(out, M, total_slots);
    k_hist<<<512, 256>>>(zidx, N, E);
    k_scan<<<1, 32>>>(E);
    k_scatter<<<(N + 255) / 256, 256>>>(zidx, N);
    k_main<<<ntiles, NTHREADS>>>(x, zidx, idxm, W1, b1, W2, b2, out);
}

// round 4
// speedup vs baseline: 1.1167x; 1.1167x over previous
#include <cuda_runtime.h>
#include <cuda_bf16.h>
#include <cstdint>

// Problem constants (this instance): N=1e6 atoms, D=128, H=64, E=4, M=20000.
#define D_DIM 128
#define H_DIM 64
#define BM 128          // atoms per tile
#define NTHREADS 256
#define E_MAX 8
#define PERM_CAP 1250000

// SMEM: bf16 tiles, row stride padded to 144 bf16 (288B) for conflict-free
// fragment loads (word index mod 32 = 8*g + tg over a warp).
#define SKP 144                     // bf16 stride
#define SKPW 72                     // u32 stride
#define A_BYTES (128 * SKP * 2)     // 36864
#define B_BYTES (64 * SKP * 2)      // 18432
#define OFF_AHI 0
#define OFF_ALO (A_BYTES)
#define OFF_BHI (2 * A_BYTES)
#define OFF_BLO (2 * A_BYTES + B_BYTES)
#define SMEM_TOTAL (2 * A_BYTES + 2 * B_BYTES)   // 110592

// ---- device scratch (no allocation in kernel_launch) ------------------------
__device__ int g_count[E_MAX];
__device__ int g_cursor[E_MAX];
__device__ int g_perm[PERM_CAP];

// ---------------------------------------------------------------------------
// prologue kernels (counting sort by element)
// ---------------------------------------------------------------------------
__global__ void k_init(float* __restrict__ out, int M, int total_slots) {
    int i = blockIdx.x * blockDim.x + threadIdx.x;
    int stride = gridDim.x * blockDim.x;
    for (int j = i; j < M; j += stride) out[j] = 0.0f;
    for (int j = i; j < total_slots; j += stride) g_perm[j] = -1;
    if (i < E_MAX) g_count[i] = 0;
}

__global__ void k_hist(const int* __restrict__ zidx, int n, int E) {
    __shared__ int sh[E_MAX];
    if (threadIdx.x < E_MAX) sh[threadIdx.x] = 0;
    __syncthreads();
    int i = blockIdx.x * blockDim.x + threadIdx.x;
    int stride = gridDim.x * blockDim.x;
    for (int j = i; j < n; j += stride) atomicAdd(&sh[zidx[j]], 1);
    __syncthreads();
    if (threadIdx.x < E) atomicAdd(&g_count[threadIdx.x], sh[threadIdx.x]);
}

__global__ void k_scan(int E) {
    if (blockIdx.x == 0 && threadIdx.x == 0) {
        int off = 0;
        for (int e = 0; e < E; e++) {
            g_cursor[e] = off;
            off += ((g_count[e] + BM - 1) / BM) * BM;
        }
    }
}

__global__ void k_scatter(const int* __restrict__ zidx, int n) {
    __shared__ int s_cnt[E_MAX];
    __shared__ int s_off[E_MAX];
    if (threadIdx.x < E_MAX) s_cnt[threadIdx.x] = 0;
    __syncthreads();
    int i = blockIdx.x * blockDim.x + threadIdx.x;
    int e = -1;
    if (i < n) { e = zidx[i]; atomicAdd(&s_cnt[e], 1); }
    __syncthreads();
    if (threadIdx.x < E_MAX && s_cnt[threadIdx.x] > 0)
        s_off[threadIdx.x] = atomicAdd(&g_cursor[threadIdx.x], s_cnt[threadIdx.x]);
    __syncthreads();
    if (threadIdx.x < E_MAX) s_cnt[threadIdx.x] = 0;
    __syncthreads();
    if (i < n) {
        int pos = s_off[e] + atomicAdd(&s_cnt[e], 1);
        g_perm[pos] = i;
    }
}

// shifted softplus: softplus(x) - log(2), numerically stable
__device__ __forceinline__ float sspf(float v) {
    return fmaxf(v, 0.0f) + log1pf(__expf(-fabsf(v))) - 0.69314718055994530942f;
}

__device__ __forceinline__ void mma_bf16(float* c, const uint32_t* a,
                                         const uint32_t* b) {
    asm volatile(
        "mma.sync.aligned.m16n8k16.row.col.f32.bf16.bf16.f32 "
        "{%0,%1,%2,%3}, {%4,%5,%6,%7}, {%8,%9}, {%0,%1,%2,%3};"
        : "+f"(c[0]), "+f"(c[1]), "+f"(c[2]), "+f"(c[3])
        : "r"(a[0]), "r"(a[1]), "r"(a[2]), "r"(a[3]), "r"(b[0]), "r"(b[1]));
}

// ---------------------------------------------------------------------------
// main kernel: gathered 128x64x128 GEMM on mma.sync bf16 (3-term hi/lo split)
// + fused ssp/W2/segment-atomic epilogue. Tiles are single-element by sort.
// ---------------------------------------------------------------------------
__global__ __launch_bounds__(NTHREADS)
void k_main(const float* __restrict__ x, const int* __restrict__ zidx,
            const int* __restrict__ idx_m,
            const float* __restrict__ W1, const float* __restrict__ b1,
            const float* __restrict__ W2, const float* __restrict__ b2,
            float* __restrict__ out) {
    extern __shared__ char smem[];
    uint32_t* AhiW = reinterpret_cast<uint32_t*>(smem + OFF_AHI);
    uint32_t* AloW = reinterpret_cast<uint32_t*>(smem + OFF_ALO);
    uint32_t* BhiW = reinterpret_cast<uint32_t*>(smem + OFF_BHI);
    uint32_t* BloW = reinterpret_cast<uint32_t*>(smem + OFF_BLO);
    __nv_bfloat16* BhiH = reinterpret_cast<__nv_bfloat16*>(smem + OFF_BHI);
    __nv_bfloat16* BloH = reinterpret_cast<__nv_bfloat16*>(smem + OFF_BLO);

    __shared__ int   s_orig[BM];
    __shared__ float b1s[H_DIM];
    __shared__ float w2s[H_DIM];
    __shared__ int   s_e;

    int tid = threadIdx.x;
    int wid = tid >> 5;
    int lane = tid & 31;
    int base_slot = blockIdx.x * BM;

    if (tid < BM) s_orig[tid] = g_perm[base_slot + tid];
    if (tid == 0) {
        int e = -1;
        for (int r = 0; r < BM; r++) {
            int o = g_perm[base_slot + r];
            if (o >= 0) { e = zidx[o]; break; }
        }
        s_e = e;
    }
    __syncthreads();
    int e = s_e;
    if (e < 0) return;  // padding-only tile (uniform exit)

    const float* W1e = W1 + (size_t)e * D_DIM * H_DIM;
    if (tid < H_DIM) {
        b1s[tid] = b1[e * H_DIM + tid];
        w2s[tid] = W2[e * H_DIM + tid];
    }

    // ---- stage A: gather x rows, hi/lo bf16 split; one warp-iter per row ----
#pragma unroll 4
    for (int p = 0; p < 16; p++) {
        int row = p * 8 + wid;
        int o = s_orig[row];
        float4 v = make_float4(0.f, 0.f, 0.f, 0.f);
        if (o >= 0)
            v = *reinterpret_cast<const float4*>(x + (size_t)o * D_DIM + lane * 4);
        __nv_bfloat16 hx = __float2bfloat16(v.x), hy = __float2bfloat16(v.y);
        __nv_bfloat16 hz = __float2bfloat16(v.z), hw = __float2bfloat16(v.w);
        float rx = v.x - __bfloat162float(hx), ry = v.y - __bfloat162float(hy);
        float rz = v.z - __bfloat162float(hz), rw = v.w - __bfloat162float(hw);
        __nv_bfloat162 hi01 = __halves2bfloat162(hx, hy);
        __nv_bfloat162 hi23 = __halves2bfloat162(hz, hw);
        __nv_bfloat162 lo01 = __floats2bfloat162_rn(rx, ry);
        __nv_bfloat162 lo23 = __floats2bfloat162_rn(rz, rw);
        uint2 hi2 = make_uint2(*reinterpret_cast<uint32_t*>(&hi01),
                               *reinterpret_cast<uint32_t*>(&hi23));
        uint2 lo2 = make_uint2(*reinterpret_cast<uint32_t*>(&lo01),
                               *reinterpret_cast<uint32_t*>(&lo23));
        int widx = row * SKPW + lane * 2;
        *reinterpret_cast<uint2*>(&AhiW[widx]) = hi2;
        *reinterpret_cast<uint2*>(&AloW[widx]) = lo2;
    }
    // ---- stage B: W1e [k][n] -> Bt[n][k] transposed, hi/lo split ----
#pragma unroll
    for (int i = 0; i < 8; i++) {
        int idx = i * NTHREADS + tid;     // 0..2047 float4s
        int k = idx >> 4;                 // 0..127
        int n4 = idx & 15;                // float4 within row
        float4 wv = *reinterpret_cast<const float4*>(W1e + (size_t)k * H_DIM + n4 * 4);
        float wa[4] = {wv.x, wv.y, wv.z, wv.w};
#pragma unroll
        for (int j = 0; j < 4; j++) {
            int n = n4 * 4 + j;
            __nv_bfloat16 h = __float2bfloat16(wa[j]);
            __nv_bfloat16 l = __float2bfloat16(wa[j] - __bfloat162float(h));
            BhiH[n * SKP + k] = h;
            BloH[n * SKP + k] = l;
        }
    }
    __syncthreads();

    // ---- mainloop: warp tile 32(m) x 32(n), 8 k-steps, 3 splits ----
    int wm = wid & 3;       // row group: rows 32*wm .. 32*wm+31
    int wn = wid >> 2;      // col group: cols 32*wn .. 32*wn+31
    int g = lane >> 2;      // groupID
    int tg = lane & 3;      // threadID in group

    float acc[2][4][4];
#pragma unroll
    for (int t = 0; t < 2; t++)
#pragma unroll
        for (int u = 0; u < 4; u++)
#pragma unroll
            for (int q = 0; q < 4; q++) acc[t][u][q] = 0.0f;

#pragma unroll
    for (int ks = 0; ks < 8; ks++) {
        int kw = ks * 8;    // u32 offset of this k16 block
        uint32_t ahi[2][4], alo[2][4], bhi[4][2], blo[4][2];
#pragma unroll
        for (int t = 0; t < 2; t++) {
            int base = (wm * 32 + t * 16 + g) * SKPW + kw + tg;
            ahi[t][0] = AhiW[base];              alo[t][0] = AloW[base];
            ahi[t][1] = AhiW[base + 8 * SKPW];   alo[t][1] = AloW[base + 8 * SKPW];
            ahi[t][2] = AhiW[base + 4];          alo[t][2] = AloW[base + 4];
            ahi[t][3] = AhiW[base + 8 * SKPW + 4]; alo[t][3] = AloW[base + 8 * SKPW + 4];
        }
#pragma unroll
        for (int u = 0; u < 4; u++) {
            int bb = (wn * 32 + u * 8 + g) * SKPW + kw + tg;
            bhi[u][0] = BhiW[bb];     bhi[u][1] = BhiW[bb + 4];
            blo[u][0] = BloW[bb];     blo[u][1] = BloW[bb + 4];
        }
#pragma unroll
        for (int t = 0; t < 2; t++)
#pragma unroll
            for (int u = 0; u < 4; u++) {
                mma_bf16(acc[t][u], ahi[t], bhi[u]);
                mma_bf16(acc[t][u], ahi[t], blo[u]);
                mma_bf16(acc[t][u], alo[t], bhi[u]);
            }
    }

    // ---- epilogue: ssp + W2 dot per row; reduce across the 4 tg lanes ----
    float b2e = b2[e];
#pragma unroll
    for (int t = 0; t < 2; t++) {
        float p0 = 0.0f, p1 = 0.0f;   // rows r0 = ..+g, r1 = r0+8
#pragma unroll
        for (int u = 0; u < 4; u++) {
            int c0 = wn * 32 + u * 8 + 2 * tg;
            p0 = fmaf(sspf(acc[t][u][0] + b1s[c0]),     w2s[c0],     p0);
            p0 = fmaf(sspf(acc[t][u][1] + b1s[c0 + 1]), w2s[c0 + 1], p0);
            p1 = fmaf(sspf(acc[t][u][2] + b1s[c0]),     w2s[c0],     p1);
            p1 = fmaf(sspf(acc[t][u][3] + b1s[c0 + 1]), w2s[c0 + 1], p1);
        }
        p0 += __shfl_xor_sync(0xffffffffu, p0, 1);
        p0 += __shfl_xor_sync(0xffffffffu, p0, 2);
        p1 += __shfl_xor_sync(0xffffffffu, p1, 1);
        p1 += __shfl_xor_sync(0xffffffffu, p1, 2);
        if (tg == 0) {
            int r0 = wm * 32 + t * 16 + g;
            int o0 = s_orig[r0];
            int o1 = s_orig[r0 + 8];
            float bias = (wn == 0) ? b2e : 0.0f;   // add b2 exactly once per row
            if (o0 >= 0) atomicAdd(&out[idx_m[o0]], p0 + bias);
            if (o1 >= 0) atomicAdd(&out[idx_m[o1]], p1 + bias);
        }
    }
}

// ---------------------------------------------------------------------------
extern "C" void kernel_launch(void* const* d_in, const int* in_sizes, int n_in,
                              void* d_out, int out_size) {
    const float* x    = (const float*)d_in[0];
    const int*   zidx = (const int*)d_in[1];
    const int*   idxm = (const int*)d_in[2];
    const float* W1   = (const float*)d_in[3];
    const float* b1   = (const float*)d_in[4];
    const float* W2   = (const float*)d_in[5];
    const float* b2   = (const float*)d_in[6];
    float* out = (float*)d_out;

    int N = in_sizes[1];
    int E = in_sizes[6];
    int M = out_size;

    int ntiles = (N + BM - 1) / BM + E;
    int total_slots = ntiles * BM;
    if (total_slots > PERM_CAP) total_slots = PERM_CAP;

    static int smem_set = 0;
    if (!smem_set) {
        cudaFuncSetAttribute(k_main, cudaFuncAttributeMaxDynamicSharedMemorySize,
                             SMEM_TOTAL);
        smem_set = 1;
    }

    k_init<<<256, 256>>>(out, M, total_slots);
    k_hist<<<512, 256>>>(zidx, N, E);
    k_scan<<<1, 32>>>(E);
    k_scatter<<<(N + 255) / 256, 256>>>(zidx, N);
    k_main<<<ntiles, NTHREADS, SMEM_TOTAL>>>(x, zidx, idxm, W1, b1, W2, b2, out);
}

// round 5
// speedup vs baseline: 1.6047x; 1.4370x over previous
#include <cuda_runtime.h>
#include <cuda_bf16.h>
#include <cstdint>

// Problem constants (this instance): N=1e6 atoms, D=128, H=64, E=4, M=20000.
#define D_DIM 128
#define H_DIM 64
#define BM 128
#define NTHREADS 256
#define E_MAX 8
#define PERM_CAP 1250000

// SMEM (bytes): A tiles [row 0..127][k-words 0..63] swizzled, B tiles
// [k 0..127][n-words 0..31] swizzled. hi/lo split buffers.
#define OFF_AHI 0
#define OFF_ALO 32768
#define OFF_BHI 65536
#define OFF_BLO 81920
#define SMEM_TOTAL 98304

__device__ int g_count[E_MAX];
__device__ int g_cursor[E_MAX];
__device__ int g_perm[PERM_CAP];

// ---------------------------------------------------------------------------
__global__ void k_dummy() {}   // aligns ncu -s 5 -c 1 onto k_main

__global__ void k_init(float* __restrict__ out, int M, int total_slots) {
    int i = blockIdx.x * blockDim.x + threadIdx.x;
    int stride = gridDim.x * blockDim.x;
    for (int j = i; j < M; j += stride) out[j] = 0.0f;
    for (int j = i; j < total_slots; j += stride) g_perm[j] = -1;
    if (i < E_MAX) g_count[i] = 0;
}

__global__ void k_hist(const int* __restrict__ zidx, int n, int E) {
    __shared__ int sh[E_MAX];
    if (threadIdx.x < E_MAX) sh[threadIdx.x] = 0;
    __syncthreads();
    int i = blockIdx.x * blockDim.x + threadIdx.x;
    int stride = gridDim.x * blockDim.x;
    for (int j = i; j < n; j += stride) atomicAdd(&sh[zidx[j]], 1);
    __syncthreads();
    if (threadIdx.x < E) atomicAdd(&g_count[threadIdx.x], sh[threadIdx.x]);
}

__global__ void k_scan(int E) {
    if (blockIdx.x == 0 && threadIdx.x == 0) {
        int off = 0;
        for (int e = 0; e < E; e++) {
            g_cursor[e] = off;
            off += ((g_count[e] + BM - 1) / BM) * BM;
        }
    }
}

__global__ void k_scatter(const int* __restrict__ zidx, int n) {
    __shared__ int s_cnt[E_MAX];
    __shared__ int s_off[E_MAX];
    if (threadIdx.x < E_MAX) s_cnt[threadIdx.x] = 0;
    __syncthreads();
    int i = blockIdx.x * blockDim.x + threadIdx.x;
    int e = -1;
    if (i < n) { e = zidx[i]; atomicAdd(&s_cnt[e], 1); }
    __syncthreads();
    if (threadIdx.x < E_MAX && s_cnt[threadIdx.x] > 0)
        s_off[threadIdx.x] = atomicAdd(&g_cursor[threadIdx.x], s_cnt[threadIdx.x]);
    __syncthreads();
    if (threadIdx.x < E_MAX) s_cnt[threadIdx.x] = 0;
    __syncthreads();
    if (i < n) {
        int pos = s_off[e] + atomicAdd(&s_cnt[e], 1);
        g_perm[pos] = i;
    }
}

__device__ __forceinline__ float sspf(float v) {
    return fmaxf(v, 0.0f) + log1pf(__expf(-fabsf(v))) - 0.69314718055994530942f;
}

__device__ __forceinline__ void mma_bf16(float* c, const uint32_t* a,
                                         const uint32_t b0, const uint32_t b1) {
    asm volatile(
        "mma.sync.aligned.m16n8k16.row.col.f32.bf16.bf16.f32 "
        "{%0,%1,%2,%3}, {%4,%5,%6,%7}, {%8,%9}, {%0,%1,%2,%3};"
        : "+f"(c[0]), "+f"(c[1]), "+f"(c[2]), "+f"(c[3])
        : "r"(a[0]), "r"(a[1]), "r"(a[2]), "r"(a[3]), "r"(b0), "r"(b1));
}
__device__ __forceinline__ void ldsm_x4(uint32_t* r, uint32_t addr) {
    asm volatile("ldmatrix.sync.aligned.m8n8.x4.shared.b16 {%0,%1,%2,%3}, [%4];"
                 : "=r"(r[0]), "=r"(r[1]), "=r"(r[2]), "=r"(r[3]) : "r"(addr));
}
__device__ __forceinline__ void ldsm_x4t(uint32_t* r, uint32_t addr) {
    asm volatile("ldmatrix.sync.aligned.m8n8.x4.trans.shared.b16 {%0,%1,%2,%3}, [%4];"
                 : "=r"(r[0]), "=r"(r[1]), "=r"(r[2]), "=r"(r[3]) : "r"(addr));
}
__device__ __forceinline__ uint32_t smem_u32(const void* p) {
    return (uint32_t)__cvta_generic_to_shared(p);
}

// ---------------------------------------------------------------------------
// main kernel: gathered 128x64x128 bf16 mma.sync GEMM (3-term hi/lo split)
// with XOR-swizzled SMEM + ldmatrix fragment loads; fused epilogue.
// ---------------------------------------------------------------------------
__global__ __launch_bounds__(NTHREADS)
void k_main(const float* __restrict__ x, const int* __restrict__ zidx,
            const int* __restrict__ idx_m,
            const float* __restrict__ W1, const float* __restrict__ b1,
            const float* __restrict__ W2, const float* __restrict__ b2,
            float* __restrict__ out) {
    extern __shared__ char smem[];
    uint32_t* AhiW = reinterpret_cast<uint32_t*>(smem + OFF_AHI);
    uint32_t* AloW = reinterpret_cast<uint32_t*>(smem + OFF_ALO);
    uint32_t* BhiW = reinterpret_cast<uint32_t*>(smem + OFF_BHI);
    uint32_t* BloW = reinterpret_cast<uint32_t*>(smem + OFF_BLO);

    __shared__ int   s_orig[BM];
    __shared__ float b1s[H_DIM];
    __shared__ float w2s[H_DIM];
    __shared__ int   s_e;

    int tid = threadIdx.x;
    int wid = tid >> 5;
    int lane = tid & 31;
    int base_slot = blockIdx.x * BM;

    if (tid < BM) s_orig[tid] = g_perm[base_slot + tid];
    if (tid == 0) {
        int e = -1;
        for (int r = 0; r < BM; r++) {
            int o = g_perm[base_slot + r];
            if (o >= 0) { e = zidx[o]; break; }
        }
        s_e = e;
    }
    __syncthreads();
    int e = s_e;
    if (e < 0) return;

    const float* W1e = W1 + (size_t)e * D_DIM * H_DIM;
    if (tid < H_DIM) {
        b1s[tid] = b1[e * H_DIM + tid];
        w2s[tid] = W2[e * H_DIM + tid];
    }

    // ---- stage A: gather x rows, hi/lo bf16 split; swizzled store ----
    // A word layout: row*64 + (wc ^ (4*(row&7))), wc = k/2
#pragma unroll 4
    for (int p = 0; p < 16; p++) {
        int row = p * 8 + wid;
        int o = s_orig[row];
        float4 v = make_float4(0.f, 0.f, 0.f, 0.f);
        if (o >= 0)
            v = *reinterpret_cast<const float4*>(x + (size_t)o * D_DIM + lane * 4);
        __nv_bfloat16 hx = __float2bfloat16(v.x), hy = __float2bfloat16(v.y);
        __nv_bfloat16 hz = __float2bfloat16(v.z), hw = __float2bfloat16(v.w);
        float rx = v.x - __bfloat162float(hx), ry = v.y - __bfloat162float(hy);
        float rz = v.z - __bfloat162float(hz), rw = v.w - __bfloat162float(hw);
        __nv_bfloat162 hi01 = __halves2bfloat162(hx, hy);
        __nv_bfloat162 hi23 = __halves2bfloat162(hz, hw);
        __nv_bfloat162 lo01 = __floats2bfloat162_rn(rx, ry);
        __nv_bfloat162 lo23 = __floats2bfloat162_rn(rz, rw);
        uint2 hi2 = make_uint2(*reinterpret_cast<uint32_t*>(&hi01),
                               *reinterpret_cast<uint32_t*>(&hi23));
        uint2 lo2 = make_uint2(*reinterpret_cast<uint32_t*>(&lo01),
                               *reinterpret_cast<uint32_t*>(&lo23));
        int w = row * 64 + ((2 * lane) ^ (4 * (row & 7)));
        *reinterpret_cast<uint2*>(&AhiW[w]) = hi2;
        *reinterpret_cast<uint2*>(&AloW[w]) = lo2;
    }
    // ---- stage B: W1e natural [k][n] layout, hi/lo split, swizzled ----
    // B word layout: k*32 + (wc ^ (4*(k&7))), wc = n/2
#pragma unroll
    for (int i = 0; i < 8; i++) {
        int idx = i * NTHREADS + tid;     // 0..2047 float4s
        int k = idx >> 4;
        int n4 = idx & 15;
        float4 wv = *reinterpret_cast<const float4*>(W1e + (size_t)k * H_DIM + n4 * 4);
        __nv_bfloat16 hx = __float2bfloat16(wv.x), hy = __float2bfloat16(wv.y);
        __nv_bfloat16 hz = __float2bfloat16(wv.z), hw = __float2bfloat16(wv.w);
        float rx = wv.x - __bfloat162float(hx), ry = wv.y - __bfloat162float(hy);
        float rz = wv.z - __bfloat162float(hz), rw = wv.w - __bfloat162float(hw);
        __nv_bfloat162 hi01 = __halves2bfloat162(hx, hy);
        __nv_bfloat162 hi23 = __halves2bfloat162(hz, hw);
        __nv_bfloat162 lo01 = __floats2bfloat162_rn(rx, ry);
        __nv_bfloat162 lo23 = __floats2bfloat162_rn(rz, rw);
        uint2 hi2 = make_uint2(*reinterpret_cast<uint32_t*>(&hi01),
                               *reinterpret_cast<uint32_t*>(&hi23));
        uint2 lo2 = make_uint2(*reinterpret_cast<uint32_t*>(&lo01),
                               *reinterpret_cast<uint32_t*>(&lo23));
        int w = k * 32 + ((n4 * 2) ^ (4 * (k & 7)));
        *reinterpret_cast<uint2*>(&BhiW[w]) = hi2;
        *reinterpret_cast<uint2*>(&BloW[w]) = lo2;
    }
    __syncthreads();

    // ---- mainloop: warp tile 32(m) x 32(n), 8 k16-steps, 3 split terms ----
    int wm = wid & 3;
    int wn = wid >> 2;
    int g = lane >> 2;
    int tg = lane & 3;
    int lane7 = lane & 7;
    int sub = lane >> 3;      // 0..3
    int subm = sub & 1;       // row +8 half
    int subh = sub >> 1;      // k/n 16B-chunk half

    uint32_t aHiBase = smem_u32(AhiW), aLoBase = smem_u32(AloW);
    uint32_t bHiBase = smem_u32(BhiW), bLoBase = smem_u32(BloW);

    // A lane address pieces: row = wm*32 + t*16 + subm*8 + lane7
    int aRowWord0 = (wm * 32 + 0 + subm * 8 + lane7) * 64;
    int aRowWord1 = (wm * 32 + 16 + subm * 8 + lane7) * 64;
    int aXor = 4 * lane7;
    int a4h = 4 * subh;
    // B lane constants: krow = kb*16 + subm*8 + lane7; nchunk = wn*4 + p*2 + subh
    int bConst0 = (subm * 8 + lane7) * 32 + ((4 * (wn * 4 + 0 + subh)) ^ (4 * lane7));
    int bConst1 = (subm * 8 + lane7) * 32 + ((4 * (wn * 4 + 2 + subh)) ^ (4 * lane7));

    float acc[2][4][4];
#pragma unroll
    for (int t = 0; t < 2; t++)
#pragma unroll
        for (int u = 0; u < 4; u++)
#pragma unroll
            for (int q = 0; q < 4; q++) acc[t][u][q] = 0.0f;

#pragma unroll
    for (int kb = 0; kb < 8; kb++) {
        int aOff = (8 * kb + a4h) ^ aXor;
        uint32_t ahi[2][4], alo[2][4], bhi[2][4], blo[2][4];
        ldsm_x4(ahi[0], aHiBase + (aRowWord0 + aOff) * 4);
        ldsm_x4(ahi[1], aHiBase + (aRowWord1 + aOff) * 4);
        ldsm_x4(alo[0], aLoBase + (aRowWord0 + aOff) * 4);
        ldsm_x4(alo[1], aLoBase + (aRowWord1 + aOff) * 4);
        ldsm_x4t(bhi[0], bHiBase + (kb * 512 + bConst0) * 4);
        ldsm_x4t(bhi[1], bHiBase + (kb * 512 + bConst1) * 4);
        ldsm_x4t(blo[0], bLoBase + (kb * 512 + bConst0) * 4);
        ldsm_x4t(blo[1], bLoBase + (kb * 512 + bConst1) * 4);
#pragma unroll
        for (int t = 0; t < 2; t++)
#pragma unroll
            for (int u = 0; u < 4; u++) {
                int p = u >> 1, q = (u & 1) * 2;
                mma_bf16(acc[t][u], ahi[t], bhi[p][q], bhi[p][q + 1]);
                mma_bf16(acc[t][u], ahi[t], blo[p][q], blo[p][q + 1]);
                mma_bf16(acc[t][u], alo[t], bhi[p][q], bhi[p][q + 1]);
            }
    }

    // ---- epilogue: ssp + W2 dot per row; reduce across the 4 tg lanes ----
    float b2e = b2[e];
#pragma unroll
    for (int t = 0; t < 2; t++) {
        float p0 = 0.0f, p1 = 0.0f;
#pragma unroll
        for (int u = 0; u < 4; u++) {
            int c0 = wn * 32 + u * 8 + 2 * tg;
            p0 = fmaf(sspf(acc[t][u][0] + b1s[c0]),     w2s[c0],     p0);
            p0 = fmaf(sspf(acc[t][u][1] + b1s[c0 + 1]), w2s[c0 + 1], p0);
            p1 = fmaf(sspf(acc[t][u][2] + b1s[c0]),     w2s[c0],     p1);
            p1 = fmaf(sspf(acc[t][u][3] + b1s[c0 + 1]), w2s[c0 + 1], p1);
        }
        p0 += __shfl_xor_sync(0xffffffffu, p0, 1);
        p0 += __shfl_xor_sync(0xffffffffu, p0, 2);
        p1 += __shfl_xor_sync(0xffffffffu, p1, 1);
        p1 += __shfl_xor_sync(0xffffffffu, p1, 2);
        if (tg == 0) {
            int r0 = wm * 32 + t * 16 + g;
            int o0 = s_orig[r0];
            int o1 = s_orig[r0 + 8];
            float bias = (wn == 0) ? b2e : 0.0f;
            if (o0 >= 0) atomicAdd(&out[idx_m[o0]], p0 + bias);
            if (o1 >= 0) atomicAdd(&out[idx_m[o1]], p1 + bias);
        }
    }
}

// ---------------------------------------------------------------------------
extern "C" void kernel_launch(void* const* d_in, const int* in_sizes, int n_in,
                              void* d_out, int out_size) {
    const float* x    = (const float*)d_in[0];
    const int*   zidx = (const int*)d_in[1];
    const int*   idxm = (const int*)d_in[2];
    const float* W1   = (const float*)d_in[3];
    const float* b1   = (const float*)d_in[4];
    const float* W2   = (const float*)d_in[5];
    const float* b2   = (const float*)d_in[6];
    float* out = (float*)d_out;

    int N = in_sizes[1];
    int E = in_sizes[6];
    int M = out_size;

    int ntiles = (N + BM - 1) / BM + E;
    int total_slots = ntiles * BM;
    if (total_slots > PERM_CAP) total_slots = PERM_CAP;

    static int smem_set = 0;
    if (!smem_set) {
        cudaFuncSetAttribute(k_main, cudaFuncAttributeMaxDynamicSharedMemorySize,
                             SMEM_TOTAL);
        smem_set = 1;
    }

    k_dummy<<<1, 32>>>();   // shifts ncu -s 5 onto k_main
    k_init<<<256, 256>>>(out, M, total_slots);
    k_hist<<<512, 256>>>(zidx, N, E);
    k_scan<<<1, 32>>>(E);
    k_scatter<<<(N + 255) / 256, 256>>>(zidx, N);
    k_main<<<ntiles, NTHREADS, SMEM_TOTAL>>>(x, zidx, idxm, W1, b1, W2, b2, out);
}